// round 4
// baseline (speedup 1.0000x reference)
#include <cuda_runtime.h>
#include <cstdint>

#define N_NODES  100000
#define N_EDGES  1600000
#define N_GRAPHS 256
#define F_IN     38
#define FP       40      // padded feature width (160B rows, 16B aligned)
#define HID      64
#define NREP     32      // replicated graph buckets for layer-2 scatter
#define NPW      64      // nodes per warp in pooling pass

// ---------------- scratch (static device globals; no allocation) ------------
__device__ __align__(256) float g_xp  [N_NODES * FP];          // 16 MB padded x
__device__ __align__(256) float g_agg1[N_NODES * FP];          // 16 MB
__device__ __align__(256) float g_h1  [N_NODES * HID];         // 25.6 MB
__device__ __align__(256) float g_S2  [NREP * N_GRAPHS * HID]; // 2 MB  (edge-sum per graph, replicated)
__device__ __align__(256) float g_Sh  [N_GRAPHS * HID];        // node-sum per graph
__device__ __align__(256) float g_cnt [N_GRAPHS];              // node counts per graph

// ---------------- vector reductions (sm_90+) --------------------------------
__device__ __forceinline__ void red4(float* p, float4 v) {
    asm volatile("red.global.add.v4.f32 [%0], {%1,%2,%3,%4};"
                 :: "l"(p), "f"(v.x), "f"(v.y), "f"(v.z), "f"(v.w) : "memory");
}
__device__ __forceinline__ void red2(float* p, float a, float b) {
    asm volatile("red.global.add.v2.f32 [%0], {%1,%2};"
                 :: "l"(p), "f"(a), "f"(b) : "memory");
}

// ---------------- K0: zero scratch + pad-copy x ------------------------------
__global__ void k_init(const float* __restrict__ x) {
    int stride = gridDim.x * blockDim.x;
    int tid    = blockIdx.x * blockDim.x + threadIdx.x;
    for (int i = tid; i < N_NODES * FP; i += stride) {
        int n = i / FP;
        int c = i - n * FP;
        g_xp[i]   = (c < F_IN) ? x[n * F_IN + c] : 0.0f;
        g_agg1[i] = 0.0f;
    }
    for (int i = tid; i < NREP * N_GRAPHS * HID; i += stride) g_S2[i] = 0.0f;
    for (int i = tid; i < N_GRAPHS * HID; i += stride)        g_Sh[i] = 0.0f;
    for (int i = tid; i < N_GRAPHS; i += stride)              g_cnt[i] = 0.0f;
}

// ---------------- K1: edge scatter of padded x (layer-1 aggregation) --------
// warp handles 2 edges: lanes 0-9 -> edge0, lanes 16-25 -> edge1 (10 x float4 = 40 floats)
__global__ void k_edge1(const int* __restrict__ ei) {
    int t    = blockIdx.x * blockDim.x + threadIdx.x;
    int gw   = t >> 5;
    int lane = t & 31;
    int e    = gw * 2 + (lane >> 4);
    int sub  = lane & 15;
    if (sub >= FP / 4) return;
    if (e >= N_EDGES) return;
    int src = ei[e];
    int dst = ei[N_EDGES + e];
    float4 v = *((const float4*)(g_xp + (size_t)src * FP) + sub);
    red4(g_agg1 + (size_t)dst * FP + sub * 4, v);
}

// ---------------- K2: per-node transform: h1 = relu(agg@Wrel + b + x@Wroot) --
__global__ __launch_bounds__(128) void k_node1(const float* __restrict__ w_rel,
                                               const float* __restrict__ b,
                                               const float* __restrict__ w_root) {
    // weights padded to FP rows (rows 38,39 zero) so the k-loop is uniform
    __shared__ __align__(16) float sW[FP * HID * 2 + HID];
    float* sWrel  = sW;
    float* sWroot = sW + FP * HID;
    float* sB     = sW + 2 * FP * HID;
    for (int i = threadIdx.x; i < FP * HID; i += blockDim.x) {
        int k = i / HID;
        int c = i - k * HID;
        sWrel[i]  = (k < F_IN) ? w_rel [k * HID + c] : 0.0f;
        sWroot[i] = (k < F_IN) ? w_root[k * HID + c] : 0.0f;
    }
    for (int i = threadIdx.x; i < HID; i += blockDim.x) sB[i] = b[i];
    __syncthreads();

    int n = blockIdx.x * blockDim.x + threadIdx.x;
    if (n >= N_NODES) return;

    float acc[HID];
#pragma unroll
    for (int c = 0; c < HID; c++) acc[c] = sB[c];

    const float4* ar = (const float4*)(g_agg1 + (size_t)n * FP);
    const float4* xr = (const float4*)(g_xp   + (size_t)n * FP);
    for (int k4 = 0; k4 < FP / 4; k4++) {
        float4 a4 = ar[k4];
        float4 x4 = xr[k4];
        float av[4] = {a4.x, a4.y, a4.z, a4.w};
        float xv[4] = {x4.x, x4.y, x4.z, x4.w};
#pragma unroll
        for (int kk = 0; kk < 4; kk++) {
            int k = k4 * 4 + kk;
            const float4* wr = (const float4*)(sWrel  + k * HID);
            const float4* wo = (const float4*)(sWroot + k * HID);
#pragma unroll
            for (int c4 = 0; c4 < HID / 4; c4++) {
                float4 w = wr[c4];
                float4 u = wo[c4];
                acc[4 * c4 + 0] = fmaf(av[kk], w.x, fmaf(xv[kk], u.x, acc[4 * c4 + 0]));
                acc[4 * c4 + 1] = fmaf(av[kk], w.y, fmaf(xv[kk], u.y, acc[4 * c4 + 1]));
                acc[4 * c4 + 2] = fmaf(av[kk], w.z, fmaf(xv[kk], u.z, acc[4 * c4 + 2]));
                acc[4 * c4 + 3] = fmaf(av[kk], w.w, fmaf(xv[kk], u.w, acc[4 * c4 + 3]));
            }
        }
    }

    float4* out = (float4*)(g_h1 + (size_t)n * HID);
#pragma unroll
    for (int c4 = 0; c4 < HID / 4; c4++) {
        float4 o;
        o.x = fmaxf(acc[4 * c4 + 0], 0.0f);
        o.y = fmaxf(acc[4 * c4 + 1], 0.0f);
        o.z = fmaxf(acc[4 * c4 + 2], 0.0f);
        o.w = fmaxf(acc[4 * c4 + 3], 0.0f);
        out[c4] = o;
    }
}

// ---------------- K3: layer-2 edge scatter DIRECTLY into graph buckets ------
// Sum over edges e with batch[dst]=g of h1[src] — never materialize per-node agg2.
// warp handles 2 edges: lanes 0-15 edge0, lanes 16-31 edge1 (16 x float4 = 64 floats)
__global__ void k_edge2(const int* __restrict__ ei,
                        const int* __restrict__ batch) {
    int t    = blockIdx.x * blockDim.x + threadIdx.x;
    int gw   = t >> 5;
    int lane = t & 31;
    int e    = gw * 2 + (lane >> 4);
    int sub  = lane & 15;
    if (e >= N_EDGES) return;
    int src = ei[e];
    int dst = ei[N_EDGES + e];
    int g   = batch[dst];
    float4 v = *((const float4*)(g_h1 + (size_t)src * HID) + sub);
    int r = gw & (NREP - 1);
    red4(g_S2 + ((size_t)(r * N_GRAPHS + g)) * HID + sub * 4, v);
}

// ---------------- K4: pool h1 (batch is SORTED -> register accumulation) ----
__global__ void k_pool(const int* __restrict__ batch) {
    int t    = blockIdx.x * blockDim.x + threadIdx.x;
    int gw   = t >> 5;
    int lane = t & 31;
    int n0   = gw * NPW;
    if (n0 >= N_NODES) return;
    int n1 = min(n0 + NPW, N_NODES);

    int cur = batch[n0];
    float2 acc = make_float2(0.0f, 0.0f);
    float cnt = 0.0f;
    for (int n = n0; n < n1; n++) {
        int g = batch[n];
        if (g != cur) {
            red2(g_Sh + cur * HID + lane * 2, acc.x, acc.y);
            if (lane == 0) atomicAdd(&g_cnt[cur], cnt);
            acc = make_float2(0.0f, 0.0f);
            cnt = 0.0f;
            cur = g;
        }
        float2 hv = *((const float2*)(g_h1 + (size_t)n * HID) + lane);
        acc.x += hv.x;
        acc.y += hv.y;
        cnt += 1.0f;
    }
    red2(g_Sh + cur * HID + lane * 2, acc.x, acc.y);
    if (lane == 0) atomicAdd(&g_cnt[cur], cnt);
}

// ---------------- K5: reduce replicas + tiny GEMM + mean + relu -------------
__global__ void k_final(const float* __restrict__ w2_rel,
                        const float* __restrict__ b2,
                        const float* __restrict__ w2_root,
                        float* __restrict__ out) {
    int g = blockIdx.x;   // 256 blocks
    int c = threadIdx.x;  // 64 threads
    __shared__ float sA[HID];
    __shared__ float sH[HID];

    float s2 = 0.0f;
#pragma unroll
    for (int r = 0; r < NREP; r++) s2 += g_S2[((size_t)(r * N_GRAPHS + g)) * HID + c];
    sA[c] = s2;
    sH[c] = g_Sh[g * HID + c];
    __syncthreads();

    float acc = 0.0f;
#pragma unroll 8
    for (int k = 0; k < HID; k++)
        acc += sA[k] * w2_rel[k * HID + c] + sH[k] * w2_root[k * HID + c];

    float n = g_cnt[g];
    acc += n * b2[c];
    out[g * HID + c] = fmaxf(acc / fmaxf(n, 1.0f), 0.0f);
}

// ---------------- launch -----------------------------------------------------
extern "C" void kernel_launch(void* const* d_in, const int* in_sizes, int n_in,
                              void* d_out, int out_size) {
    const float* x       = (const float*)d_in[0];
    const int*   ei      = (const int*)d_in[1];    // int32: JAX x64 disabled
    const int*   batch   = (const int*)d_in[2];    // int32
    const float* w1_rel  = (const float*)d_in[3];
    const float* b1_rel  = (const float*)d_in[4];
    const float* w1_root = (const float*)d_in[5];
    const float* w2_rel  = (const float*)d_in[6];
    const float* b2_rel  = (const float*)d_in[7];
    const float* w2_root = (const float*)d_in[8];
    float*       out     = (float*)d_out;

    k_init <<<1024, 256>>>(x);
    k_edge1<<<N_EDGES / 16, 256>>>(ei);                     // 8 warps * 2 edges = 16 edges/block
    k_node1<<<(N_NODES + 127) / 128, 128>>>(w1_rel, b1_rel, w1_root);
    k_edge2<<<N_EDGES / 16, 256>>>(ei, batch);
    k_pool <<<(N_NODES + NPW * 4 - 1) / (NPW * 4), 128>>>(batch);
    k_final<<<N_GRAPHS, HID>>>(w2_rel, b2_rel, w2_root, out);
}

// round 6
// speedup vs baseline: 1.0705x; 1.0705x over previous
#include <cuda_runtime.h>
#include <cuda_fp16.h>
#include <cstdint>

#define N_NODES  100000
#define N_EDGES  1600000
#define N_GRAPHS 256
#define F_IN     38
#define FP       40      // padded feature width (80B half rows, 16B aligned)
#define HID      64
#define NREP     32      // replicated graph buckets for scatters

typedef unsigned long long ull;

// ---------------- scratch (static device globals; no allocation) ------------
__device__ __align__(256) __half g_xh  [N_NODES * FP];          // 8 MB   padded x (half)
__device__ __align__(256) float  g_agg1[N_NODES * FP];          // 16 MB  layer-1 edge sums (f32)
__device__ __align__(256) __half g_h1h [N_NODES * HID];         // 12.8MB relu(h1) (half)
__device__ __align__(256) float  g_S2  [NREP * N_GRAPHS * HID]; // 2 MB   layer-2 edge-sum buckets
__device__ __align__(256) float  g_Shr [NREP * N_GRAPHS * HID]; // 2 MB   node-sum buckets
__device__ __align__(256) float  g_cntr[NREP * N_GRAPHS];       // 32 KB  node counts

// ---------------- helpers ----------------------------------------------------
__device__ __forceinline__ void red4(float* p, float a, float b, float c, float d) {
    asm volatile("red.global.add.v4.f32 [%0], {%1,%2,%3,%4};"
                 :: "l"(p), "f"(a), "f"(b), "f"(c), "f"(d) : "memory");
}
__device__ __forceinline__ ull pk2(float a) {          // pack (a,a) into f32x2
    ull r; asm("mov.b64 %0, {%1, %1};" : "=l"(r) : "f"(a)); return r;
}
__device__ __forceinline__ void fma2(ull& d, ull a, ull b) {   // d += a*b (packed f32x2)
    asm("fma.rn.f32x2 %0, %1, %2, %0;" : "+l"(d) : "l"(a), "l"(b));
}
__device__ __forceinline__ float2 upk2(ull v) {
    float2 f; asm("mov.b64 {%0, %1}, %2;" : "=f"(f.x), "=f"(f.y) : "l"(v)); return f;
}

// ---------------- K0: zero scratch + pad-convert x to half -------------------
__global__ void k_init(const float* __restrict__ x) {
    int stride = gridDim.x * blockDim.x;
    int tid    = blockIdx.x * blockDim.x + threadIdx.x;
    for (int i = tid; i < N_NODES * FP; i += stride) {
        int n = i / FP;
        int c = i - n * FP;
        g_xh[i] = (c < F_IN) ? __float2half(x[n * F_IN + c]) : __half(0.0f);
    }
    float4 z4 = make_float4(0.f, 0.f, 0.f, 0.f);
    for (int i = tid; i < N_NODES * FP / 4; i += stride)        ((float4*)g_agg1)[i] = z4;
    for (int i = tid; i < NREP * N_GRAPHS * HID / 4; i += stride) {
        ((float4*)g_S2)[i]  = z4;
        ((float4*)g_Shr)[i] = z4;
    }
    for (int i = tid; i < NREP * N_GRAPHS; i += stride)         g_cntr[i] = 0.0f;
}

// ---------------- K1: layer-1 edge scatter (half gather -> f32 red) ----------
// warp = 6 edges x 5 lanes; each lane: uint4 = 8 halves -> 2x red4 (f32)
__global__ void k_edge1(const int* __restrict__ ei) {
    int t    = blockIdx.x * blockDim.x + threadIdx.x;
    int gw   = t >> 5;
    int lane = t & 31;
    if (lane >= 30) return;
    int le   = lane / 5;               // 0..5 within warp
    int sub  = lane - le * 5;          // 0..4
    int e    = gw * 6 + le;
    if (e >= N_EDGES) return;
    int src = ei[e];
    int dst = ei[N_EDGES + e];
    uint4 v = *((const uint4*)(g_xh + (size_t)src * FP) + sub);
    const __half2* hp = (const __half2*)&v;
    float2 f0 = __half22float2(hp[0]);
    float2 f1 = __half22float2(hp[1]);
    float2 f2 = __half22float2(hp[2]);
    float2 f3 = __half22float2(hp[3]);
    float* base = g_agg1 + (size_t)dst * FP + sub * 8;
    red4(base,     f0.x, f0.y, f1.x, f1.y);
    red4(base + 4, f2.x, f2.y, f3.x, f3.y);
}

// ---------------- K2: node transform + fused pooling -------------------------
// h1 = relu(agg1@W1rel + b1 + x@W1root); write h1 as half; red h1 row into
// replicated graph node-sum buckets; atomic count.
__global__ __launch_bounds__(128) void k_node1(const float* __restrict__ w_rel,
                                               const float* __restrict__ b,
                                               const float* __restrict__ w_root,
                                               const int*   __restrict__ batch) {
    __shared__ __align__(16) float sW[FP * HID * 2 + HID];
    float* sWrel  = sW;
    float* sWroot = sW + FP * HID;
    float* sB     = sW + 2 * FP * HID;
    for (int i = threadIdx.x; i < FP * HID; i += blockDim.x) {
        int k = i / HID;
        int c = i - k * HID;
        sWrel[i]  = (k < F_IN) ? w_rel [k * HID + c] : 0.0f;
        sWroot[i] = (k < F_IN) ? w_root[k * HID + c] : 0.0f;
    }
    for (int i = threadIdx.x; i < HID; i += blockDim.x) sB[i] = b[i];
    __syncthreads();

    int n = blockIdx.x * blockDim.x + threadIdx.x;
    if (n >= N_NODES) return;

    ull acc2[HID / 2];
#pragma unroll
    for (int j = 0; j < HID / 2; j++) acc2[j] = ((const ull*)sB)[j];

    const float4* ar  = (const float4*)(g_agg1 + (size_t)n * FP);
    const uint4*  xrh = (const uint4*) (g_xh   + (size_t)n * FP);

    for (int ch = 0; ch < 5; ch++) {                    // 5 chunks of 8 k-values
        float4 a0 = ar[2 * ch];
        float4 a1 = ar[2 * ch + 1];
        uint4  xv = xrh[ch];
        const __half2* hp = (const __half2*)&xv;
        float av[8] = {a0.x, a0.y, a0.z, a0.w, a1.x, a1.y, a1.z, a1.w};
        float xf[8];
#pragma unroll
        for (int j = 0; j < 4; j++) {
            float2 f = __half22float2(hp[j]);
            xf[2 * j] = f.x; xf[2 * j + 1] = f.y;
        }
#pragma unroll
        for (int kk = 0; kk < 8; kk++) {
            int k = ch * 8 + kk;
            ull a2 = pk2(av[kk]);
            ull x2 = pk2(xf[kk]);
            const ulonglong2* wr = (const ulonglong2*)(sWrel  + k * HID);
            const ulonglong2* wo = (const ulonglong2*)(sWroot + k * HID);
#pragma unroll
            for (int c4 = 0; c4 < HID / 4; c4++) {
                ulonglong2 w = wr[c4];
                ulonglong2 u = wo[c4];
                fma2(acc2[2 * c4],     a2, w.x);
                fma2(acc2[2 * c4 + 1], a2, w.y);
                fma2(acc2[2 * c4],     x2, u.x);
                fma2(acc2[2 * c4 + 1], x2, u.y);
            }
        }
    }

    // unpack + relu
    float val[HID];
#pragma unroll
    for (int j = 0; j < HID / 2; j++) {
        float2 f = upk2(acc2[j]);
        val[2 * j]     = fmaxf(f.x, 0.0f);
        val[2 * j + 1] = fmaxf(f.y, 0.0f);
    }

    // write h1 as half (128B row = 8 uint4s, 8 halves each)  [FIXED INDEXING]
    uint4* out = (uint4*)(g_h1h + (size_t)n * HID);
#pragma unroll
    for (int q = 0; q < 8; q++) {
        uint4 o;
        unsigned* op = (unsigned*)&o;
#pragma unroll
        for (int j = 0; j < 4; j++) {
            __half2 h = __floats2half2_rn(val[q * 8 + 2 * j], val[q * 8 + 2 * j + 1]);
            op[j] = *(unsigned*)&h;
        }
        out[q] = o;
    }

    // fused pooling: red h1 row into replicated node-sum bucket
    int g = batch[n];
    int r = n & (NREP - 1);
    float* base = g_Shr + ((size_t)(r * N_GRAPHS + g)) * HID;
#pragma unroll
    for (int i = 0; i < HID / 4; i++)
        red4(base + 4 * i, val[4 * i], val[4 * i + 1], val[4 * i + 2], val[4 * i + 3]);
    atomicAdd(&g_cntr[r * N_GRAPHS + g], 1.0f);
}

// ---------------- K3: layer-2 edge scatter into graph buckets ----------------
// warp = 4 edges x 8 lanes; each lane: uint4 = 8 halves -> 2x red4 (f32)
__global__ void k_edge2(const int* __restrict__ ei,
                        const int* __restrict__ batch) {
    int t    = blockIdx.x * blockDim.x + threadIdx.x;
    int gw   = t >> 5;
    int lane = t & 31;
    int e    = gw * 4 + (lane >> 3);
    int sub  = lane & 7;
    if (e >= N_EDGES) return;
    int src = ei[e];
    int dst = ei[N_EDGES + e];
    int g   = batch[dst];
    uint4 v = *((const uint4*)(g_h1h + (size_t)src * HID) + sub);
    const __half2* hp = (const __half2*)&v;
    float2 f0 = __half22float2(hp[0]);
    float2 f1 = __half22float2(hp[1]);
    float2 f2 = __half22float2(hp[2]);
    float2 f3 = __half22float2(hp[3]);
    int r = gw & (NREP - 1);
    float* base = g_S2 + ((size_t)(r * N_GRAPHS + g)) * HID + sub * 8;
    red4(base,     f0.x, f0.y, f1.x, f1.y);
    red4(base + 4, f2.x, f2.y, f3.x, f3.y);
}

// ---------------- K4: reduce replicas + tiny GEMM + mean + relu --------------
__global__ void k_final(const float* __restrict__ w2_rel,
                        const float* __restrict__ b2,
                        const float* __restrict__ w2_root,
                        float* __restrict__ out) {
    int g = blockIdx.x;   // 256 blocks
    int c = threadIdx.x;  // 64 threads
    __shared__ float sA[HID];
    __shared__ float sH[HID];
    __shared__ float sc;

    float s2 = 0.0f, sh = 0.0f;
#pragma unroll
    for (int r = 0; r < NREP; r++) {
        s2 += g_S2 [((size_t)(r * N_GRAPHS + g)) * HID + c];
        sh += g_Shr[((size_t)(r * N_GRAPHS + g)) * HID + c];
    }
    sA[c] = s2;
    sH[c] = sh;
    if (c == 0) {
        float n = 0.0f;
#pragma unroll
        for (int r = 0; r < NREP; r++) n += g_cntr[r * N_GRAPHS + g];
        sc = n;
    }
    __syncthreads();

    float acc = 0.0f;
#pragma unroll 8
    for (int k = 0; k < HID; k++)
        acc += sA[k] * w2_rel[k * HID + c] + sH[k] * w2_root[k * HID + c];

    float n = sc;
    acc += n * b2[c];
    out[g * HID + c] = fmaxf(acc / fmaxf(n, 1.0f), 0.0f);
}

// ---------------- launch -----------------------------------------------------
extern "C" void kernel_launch(void* const* d_in, const int* in_sizes, int n_in,
                              void* d_out, int out_size) {
    const float* x       = (const float*)d_in[0];
    const int*   ei      = (const int*)d_in[1];    // int32
    const int*   batch   = (const int*)d_in[2];    // int32
    const float* w1_rel  = (const float*)d_in[3];
    const float* b1_rel  = (const float*)d_in[4];
    const float* w1_root = (const float*)d_in[5];
    const float* w2_rel  = (const float*)d_in[6];
    const float* b2_rel  = (const float*)d_in[7];
    const float* w2_root = (const float*)d_in[8];
    float*       out     = (float*)d_out;

    k_init <<<2048, 256>>>(x);
    k_edge1<<<(N_EDGES + 47) / 48, 256>>>(ei);              // 8 warps * 6 edges
    k_node1<<<(N_NODES + 127) / 128, 128>>>(w1_rel, b1_rel, w1_root, batch);
    k_edge2<<<(N_EDGES + 31) / 32, 256>>>(ei, batch);       // 8 warps * 4 edges
    k_final<<<N_GRAPHS, HID>>>(w2_rel, b2_rel, w2_root, out);
}

// round 7
// speedup vs baseline: 1.2482x; 1.1659x over previous
#include <cuda_runtime.h>
#include <cuda_fp16.h>
#include <cstdint>

#define N_NODES  100000
#define N_EDGES  1600000
#define N_GRAPHS 256
#define F_IN     38
#define FP       40      // padded feature width (80B half rows)
#define HID      64
#define NREP     32      // replicated graph buckets
#define NSB      98      // scan blocks (98*1024 = 100352 bins >= N_NODES)
#define NBINS    (NSB * 1024)
#define CHUNK    128     // edges per warp in sorted-consume kernels

typedef unsigned long long ull;

// ---------------- scratch (static device globals; no allocation) ------------
__device__ __align__(256) __half   g_xh  [N_NODES * FP];          // 8 MB
__device__ __align__(256) float    g_agg1[N_NODES * FP];          // 16 MB
__device__ __align__(256) __half   g_h1h [N_NODES * HID];         // 12.8MB
__device__ __align__(256) float    g_S2  [NREP * N_GRAPHS * HID]; // 2 MB
__device__ __align__(256) float    g_Shr [NREP * N_GRAPHS * HID]; // 2 MB
__device__ __align__(256) float    g_cntr[NREP * N_GRAPHS];       // 32 KB
__device__ __align__(256) unsigned g_dcnt[NBINS];                 // 400 KB hist
__device__ __align__(256) unsigned g_base[NBINS];                 // 400 KB base/cursor
__device__ __align__(256) unsigned g_bsum[128];
__device__ __align__(256) ull      g_rec [N_EDGES];               // 12.8 MB sorted records

// ---------------- helpers (NO memory clobber: reds alias nothing we read) ----
__device__ __forceinline__ void red4(float* p, float a, float b, float c, float d) {
    asm volatile("red.global.add.v4.f32 [%0], {%1,%2,%3,%4};"
                 :: "l"(p), "f"(a), "f"(b), "f"(c), "f"(d));
}
__device__ __forceinline__ void red2(float* p, float a, float b) {
    asm volatile("red.global.add.v2.f32 [%0], {%1,%2};"
                 :: "l"(p), "f"(a), "f"(b));
}
__device__ __forceinline__ ull pk2(float a) {
    ull r; asm("mov.b64 %0, {%1, %1};" : "=l"(r) : "f"(a)); return r;
}
__device__ __forceinline__ void fma2(ull& d, ull a, ull b) {
    asm("fma.rn.f32x2 %0, %1, %2, %0;" : "+l"(d) : "l"(a), "l"(b));
}
__device__ __forceinline__ float2 upk2(ull v) {
    float2 f; asm("mov.b64 {%0, %1}, %2;" : "=f"(f.x), "=f"(f.y) : "l"(v)); return f;
}

// ---------------- K0: zero scratch + pad-convert x to half -------------------
__global__ void k_init(const float* __restrict__ x) {
    int stride = gridDim.x * blockDim.x;
    int tid    = blockIdx.x * blockDim.x + threadIdx.x;
    for (int i = tid; i < N_NODES * FP; i += stride) {
        int n = i / FP;
        int c = i - n * FP;
        g_xh[i] = (c < F_IN) ? __float2half(x[n * F_IN + c]) : __half(0.0f);
    }
    float4 z4 = make_float4(0.f, 0.f, 0.f, 0.f);
    for (int i = tid; i < N_NODES * FP / 4; i += stride)          ((float4*)g_agg1)[i] = z4;
    for (int i = tid; i < NREP * N_GRAPHS * HID / 4; i += stride) {
        ((float4*)g_S2)[i]  = z4;
        ((float4*)g_Shr)[i] = z4;
    }
    for (int i = tid; i < NREP * N_GRAPHS; i += stride)           g_cntr[i] = 0.0f;
    for (int i = tid; i < NBINS; i += stride)                     g_dcnt[i] = 0u;
}

// ---------------- S1: histogram over dst -------------------------------------
__global__ void k_hist(const int* __restrict__ ei) {
    int stride = gridDim.x * blockDim.x;
    for (int e = blockIdx.x * blockDim.x + threadIdx.x; e < N_EDGES; e += stride)
        atomicAdd(&g_dcnt[ei[N_EDGES + e]], 1u);
}

// ---------------- S2: per-block exclusive scan (1024 bins/block) --------------
__global__ void k_scan1() {
    __shared__ unsigned s[1024];
    int b = blockIdx.x, t = threadIdx.x;
    int i = b * 1024 + t;
    unsigned v = g_dcnt[i];
    s[t] = v;
    __syncthreads();
    for (int off = 1; off < 1024; off <<= 1) {
        unsigned a = (t >= off) ? s[t - off] : 0u;
        __syncthreads();
        s[t] += a;
        __syncthreads();
    }
    g_base[i] = s[t] - v;                 // exclusive
    if (t == 1023) g_bsum[b] = s[t];      // block total
}

// ---------------- S3: add block offsets --------------------------------------
__global__ void k_scan2() {
    __shared__ unsigned sb[128];
    __shared__ unsigned soff;
    int b = blockIdx.x, t = threadIdx.x;
    if (t < NSB) sb[t] = g_bsum[t];
    __syncthreads();
    if (t == 0) {
        unsigned s = 0;
        for (int i = 0; i < b; i++) s += sb[i];
        soff = s;
    }
    __syncthreads();
    g_base[b * 1024 + t] += soff;
}

// ---------------- S4: scatter edges into dst-sorted records -------------------
// record: src [0..19] | dst [20..39] | g [40..47]
__global__ void k_scatter(const int* __restrict__ ei, const int* __restrict__ batch) {
    int stride = gridDim.x * blockDim.x;
    for (int e = blockIdx.x * blockDim.x + threadIdx.x; e < N_EDGES; e += stride) {
        unsigned src = (unsigned)ei[e];
        unsigned dst = (unsigned)ei[N_EDGES + e];
        unsigned g   = (unsigned)batch[dst];
        unsigned pos = atomicAdd(&g_base[dst], 1u);   // base array doubles as cursor
        g_rec[pos] = (ull)src | ((ull)dst << 20) | ((ull)g << 40);
    }
}

// ---------------- K1: sorted layer-1 aggregation ------------------------------
// warp walks CHUNK consecutive edges; register-accumulate x[src] per dst run.
__global__ void k_edge1s() {
    int t    = blockIdx.x * blockDim.x + threadIdx.x;
    int w    = t >> 5;
    int lane = t & 31;
    int e0   = w * CHUNK;
    if (e0 >= N_EDGES) return;                         // N_EDGES/CHUNK exact

    float ax = 0.f, ay = 0.f;
    int cur = -1;
    const ull* R = g_rec;
#pragma unroll 4
    for (int e = e0; e < e0 + CHUNK; e += 2) {
        ulonglong2 rr = *(const ulonglong2*)(R + e);   // broadcast, 2 records
        int srcA = (int)(rr.x & 0xFFFFF), dstA = (int)((rr.x >> 20) & 0xFFFFF);
        int srcB = (int)(rr.y & 0xFFFFF), dstB = (int)((rr.y >> 20) & 0xFFFFF);
        float2 fA = make_float2(0.f, 0.f), fB = make_float2(0.f, 0.f);
        if (lane < FP / 2) {
            fA = __half22float2(*(const __half2*)(g_xh + (size_t)srcA * FP + lane * 2));
            fB = __half22float2(*(const __half2*)(g_xh + (size_t)srcB * FP + lane * 2));
        }
        if (dstA != cur) {
            if (cur >= 0 && lane < FP / 2) red2(g_agg1 + (size_t)cur * FP + lane * 2, ax, ay);
            ax = 0.f; ay = 0.f; cur = dstA;
        }
        ax += fA.x; ay += fA.y;
        if (dstB != cur) {
            if (lane < FP / 2) red2(g_agg1 + (size_t)cur * FP + lane * 2, ax, ay);
            ax = 0.f; ay = 0.f; cur = dstB;
        }
        ax += fB.x; ay += fB.y;
    }
    if (cur >= 0 && lane < FP / 2) red2(g_agg1 + (size_t)cur * FP + lane * 2, ax, ay);
}

// ---------------- K2: node transform + fused pooling (unchanged, passed) -----
__global__ __launch_bounds__(128) void k_node1(const float* __restrict__ w_rel,
                                               const float* __restrict__ b,
                                               const float* __restrict__ w_root,
                                               const int*   __restrict__ batch) {
    __shared__ __align__(16) float sW[FP * HID * 2 + HID];
    float* sWrel  = sW;
    float* sWroot = sW + FP * HID;
    float* sB     = sW + 2 * FP * HID;
    for (int i = threadIdx.x; i < FP * HID; i += blockDim.x) {
        int k = i / HID;
        int c = i - k * HID;
        sWrel[i]  = (k < F_IN) ? w_rel [k * HID + c] : 0.0f;
        sWroot[i] = (k < F_IN) ? w_root[k * HID + c] : 0.0f;
    }
    for (int i = threadIdx.x; i < HID; i += blockDim.x) sB[i] = b[i];
    __syncthreads();

    int n = blockIdx.x * blockDim.x + threadIdx.x;
    if (n >= N_NODES) return;

    ull acc2[HID / 2];
#pragma unroll
    for (int j = 0; j < HID / 2; j++) acc2[j] = ((const ull*)sB)[j];

    const float4* ar  = (const float4*)(g_agg1 + (size_t)n * FP);
    const uint4*  xrh = (const uint4*) (g_xh   + (size_t)n * FP);

    for (int ch = 0; ch < 5; ch++) {
        float4 a0 = ar[2 * ch];
        float4 a1 = ar[2 * ch + 1];
        uint4  xv = xrh[ch];
        const __half2* hp = (const __half2*)&xv;
        float av[8] = {a0.x, a0.y, a0.z, a0.w, a1.x, a1.y, a1.z, a1.w};
        float xf[8];
#pragma unroll
        for (int j = 0; j < 4; j++) {
            float2 f = __half22float2(hp[j]);
            xf[2 * j] = f.x; xf[2 * j + 1] = f.y;
        }
#pragma unroll
        for (int kk = 0; kk < 8; kk++) {
            int k = ch * 8 + kk;
            ull a2 = pk2(av[kk]);
            ull x2 = pk2(xf[kk]);
            const ulonglong2* wr = (const ulonglong2*)(sWrel  + k * HID);
            const ulonglong2* wo = (const ulonglong2*)(sWroot + k * HID);
#pragma unroll
            for (int c4 = 0; c4 < HID / 4; c4++) {
                ulonglong2 w = wr[c4];
                ulonglong2 u = wo[c4];
                fma2(acc2[2 * c4],     a2, w.x);
                fma2(acc2[2 * c4 + 1], a2, w.y);
                fma2(acc2[2 * c4],     x2, u.x);
                fma2(acc2[2 * c4 + 1], x2, u.y);
            }
        }
    }

    float val[HID];
#pragma unroll
    for (int j = 0; j < HID / 2; j++) {
        float2 f = upk2(acc2[j]);
        val[2 * j]     = fmaxf(f.x, 0.0f);
        val[2 * j + 1] = fmaxf(f.y, 0.0f);
    }

    uint4* out = (uint4*)(g_h1h + (size_t)n * HID);
#pragma unroll
    for (int q = 0; q < 8; q++) {
        uint4 o;
        unsigned* op = (unsigned*)&o;
#pragma unroll
        for (int j = 0; j < 4; j++) {
            __half2 h = __floats2half2_rn(val[q * 8 + 2 * j], val[q * 8 + 2 * j + 1]);
            op[j] = *(unsigned*)&h;
        }
        out[q] = o;
    }

    int g = batch[n];
    int r = n & (NREP - 1);
    float* base = g_Shr + ((size_t)(r * N_GRAPHS + g)) * HID;
#pragma unroll
    for (int i = 0; i < HID / 4; i++)
        red4(base + 4 * i, val[4 * i], val[4 * i + 1], val[4 * i + 2], val[4 * i + 3]);
    atomicAdd(&g_cntr[r * N_GRAPHS + g], 1.0f);
}

// ---------------- K3: sorted layer-2 aggregation (g non-decreasing) ----------
__global__ void k_edge2s() {
    int t    = blockIdx.x * blockDim.x + threadIdx.x;
    int w    = t >> 5;
    int lane = t & 31;
    int e0   = w * CHUNK;
    if (e0 >= N_EDGES) return;
    int r = w & (NREP - 1);

    float ax = 0.f, ay = 0.f;
    int cur = -1;
    const ull* R = g_rec;
#pragma unroll 4
    for (int e = e0; e < e0 + CHUNK; e += 2) {
        ulonglong2 rr = *(const ulonglong2*)(R + e);
        int srcA = (int)(rr.x & 0xFFFFF), gA = (int)((rr.x >> 40) & 0xFF);
        int srcB = (int)(rr.y & 0xFFFFF), gB = (int)((rr.y >> 40) & 0xFF);
        float2 fA = __half22float2(*(const __half2*)(g_h1h + (size_t)srcA * HID + lane * 2));
        float2 fB = __half22float2(*(const __half2*)(g_h1h + (size_t)srcB * HID + lane * 2));
        if (gA != cur) {
            if (cur >= 0) red2(g_S2 + ((size_t)(r * N_GRAPHS + cur)) * HID + lane * 2, ax, ay);
            ax = 0.f; ay = 0.f; cur = gA;
        }
        ax += fA.x; ay += fA.y;
        if (gB != cur) {
            red2(g_S2 + ((size_t)(r * N_GRAPHS + cur)) * HID + lane * 2, ax, ay);
            ax = 0.f; ay = 0.f; cur = gB;
        }
        ax += fB.x; ay += fB.y;
    }
    if (cur >= 0) red2(g_S2 + ((size_t)(r * N_GRAPHS + cur)) * HID + lane * 2, ax, ay);
}

// ---------------- K4: reduce replicas + tiny GEMM + mean + relu --------------
__global__ void k_final(const float* __restrict__ w2_rel,
                        const float* __restrict__ b2,
                        const float* __restrict__ w2_root,
                        float* __restrict__ out) {
    int g = blockIdx.x;
    int c = threadIdx.x;
    __shared__ float sA[HID];
    __shared__ float sH[HID];
    __shared__ float sc;

    float s2 = 0.0f, sh = 0.0f;
#pragma unroll
    for (int r = 0; r < NREP; r++) {
        s2 += g_S2 [((size_t)(r * N_GRAPHS + g)) * HID + c];
        sh += g_Shr[((size_t)(r * N_GRAPHS + g)) * HID + c];
    }
    sA[c] = s2;
    sH[c] = sh;
    if (c == 0) {
        float n = 0.0f;
#pragma unroll
        for (int r = 0; r < NREP; r++) n += g_cntr[r * N_GRAPHS + g];
        sc = n;
    }
    __syncthreads();

    float acc = 0.0f;
#pragma unroll 8
    for (int k = 0; k < HID; k++)
        acc += sA[k] * w2_rel[k * HID + c] + sH[k] * w2_root[k * HID + c];

    float n = sc;
    acc += n * b2[c];
    out[g * HID + c] = fmaxf(acc / fmaxf(n, 1.0f), 0.0f);
}

// ---------------- launch -----------------------------------------------------
extern "C" void kernel_launch(void* const* d_in, const int* in_sizes, int n_in,
                              void* d_out, int out_size) {
    const float* x       = (const float*)d_in[0];
    const int*   ei      = (const int*)d_in[1];
    const int*   batch   = (const int*)d_in[2];
    const float* w1_rel  = (const float*)d_in[3];
    const float* b1_rel  = (const float*)d_in[4];
    const float* w1_root = (const float*)d_in[5];
    const float* w2_rel  = (const float*)d_in[6];
    const float* b2_rel  = (const float*)d_in[7];
    const float* w2_root = (const float*)d_in[8];
    float*       out     = (float*)d_out;

    int nwarp = N_EDGES / CHUNK;                       // 12500, exact
    int ncta  = (nwarp * 32 + 255) / 256;              // 1563

    k_init   <<<2048, 256>>>(x);
    k_hist   <<<2048, 256>>>(ei);
    k_scan1  <<<NSB, 1024>>>();
    k_scan2  <<<NSB, 1024>>>();
    k_scatter<<<2048, 256>>>(ei, batch);
    k_edge1s <<<ncta, 256>>>();
    k_node1  <<<(N_NODES + 127) / 128, 128>>>(w1_rel, b1_rel, w1_root, batch);
    k_edge2s <<<ncta, 256>>>();
    k_final  <<<N_GRAPHS, HID>>>(w2_rel, b2_rel, w2_root, out);
}